// round 3
// baseline (speedup 1.0000x reference)
#include <cuda_runtime.h>
#include <cuda_bf16.h>
#include <math.h>

// Problem dims
#define BB   64
#define N1   1152
#define PP   8
#define N2   128
#define DD   16
#define NDD  (N2 * DD)          // 2048
#define WI   (N2 * DD * PP)     // 16384 : W stride per i  (fixed from round 0!)

#define I_B  64                 // i's per block
#define BG   8                  // b's per block
#define NBI  (N1 / I_B)         // 18
#define NBB  (BB / BG)          // 8
#define NT   512                // 16 warps

// Scratch (no allocations allowed -> device globals)
__device__ float g_partial[NBI * BB * NDD];   // 9.44 MB per-(iblock,b) partials
__device__ float g_v0[BB * NDD];              // squashed v after iteration 0

// ---------------------------------------------------------------------------
// One kernel, two modes.
//   ROUTE=false: sacc += pred                      (iteration 0, c uniform)
//   ROUTE=true : raw=<pred,v0>, softmax_n, sacc += c*pred   (iteration 1)
// Mapping: warp w owns n in [8w, 8w+8); lane l: n = 8w + (l>>2),
//          d in [(l&3)*4, (l&3)*4+4). W frag (32 floats) in registers per i,
//          reused across the 8 b's of this block.
// ---------------------------------------------------------------------------
template<bool ROUTE>
__global__ __launch_bounds__(NT) void caps_pass(
    const float* __restrict__ x, const float* __restrict__ W,
    const float* __restrict__ v0)
{
    __shared__ float  x_sh[BG][I_B * PP];   // 16 KB
    __shared__ float2 red[2][16];           // (max, expsum) per warp, double-buffered

    const int tid = threadIdx.x;
    const int w   = tid >> 5;
    const int l   = tid & 31;
    const int n   = w * 8 + (l >> 2);       // this lane's capsule
    const int dq  = (l & 3) * 4;            // this lane's d base
    const int ib0 = blockIdx.x * I_B;
    const int b0  = blockIdx.y * BG;

    // stage x tile: x[b0..b0+8)[ib0..ib0+64)[8]
    for (int t = tid; t < BG * I_B * PP; t += NT) {
        const int bb  = t / (I_B * PP);
        const int rem = t - bb * (I_B * PP);
        x_sh[bb][rem] = x[(size_t)(b0 + bb) * N1 * PP + (size_t)ib0 * PP + rem];
    }

    // v0 fragment for this lane (4 d's per b), registers
    float v0r[BG][4];
    if (ROUTE) {
#pragma unroll
        for (int bb = 0; bb < BG; ++bb) {
            const float4 t = *(const float4*)(v0 + (size_t)(b0 + bb) * NDD + n * DD + dq);
            v0r[bb][0] = t.x; v0r[bb][1] = t.y; v0r[bb][2] = t.z; v0r[bb][3] = t.w;
        }
    }
    __syncthreads();

    float sacc[BG][4];
#pragma unroll
    for (int bb = 0; bb < BG; ++bb)
#pragma unroll
        for (int j = 0; j < 4; ++j) sacc[bb][j] = 0.0f;

    int buf = 0;
#pragma unroll 1
    for (int ii = 0; ii < I_B; ++ii) {
        // W fragment: W[i, n, dq+j, p]  j=0..3, p=0..7  -> 8 float4 in regs
        const float4* Wp = (const float4*)(W + (size_t)(ib0 + ii) * WI + n * (DD * PP) + dq * PP);
        float4 wv[8];
#pragma unroll
        for (int q = 0; q < 8; ++q) wv[q] = Wp[q];

#pragma unroll
        for (int bb = 0; bb < BG; ++bb) {
            const float4 xa = *(const float4*)&x_sh[bb][ii * PP];
            const float4 xb = *(const float4*)&x_sh[bb][ii * PP + 4];

            float pr[4];
#pragma unroll
            for (int j = 0; j < 4; ++j) {
                const float4 w0 = wv[2 * j];
                const float4 w1 = wv[2 * j + 1];
                pr[j] = w0.x * xa.x + w0.y * xa.y + w0.z * xa.z + w0.w * xa.w
                      + w1.x * xb.x + w1.y * xb.y + w1.z * xb.z + w1.w * xb.w;
            }

            if (ROUTE) {
                // agreement logit: quad holds the 16 d's of this n
                float r = pr[0] * v0r[bb][0] + pr[1] * v0r[bb][1]
                        + pr[2] * v0r[bb][2] + pr[3] * v0r[bb][3];
                r += __shfl_xor_sync(0xFFFFFFFFu, r, 1);
                r += __shfl_xor_sync(0xFFFFFFFFu, r, 2);

                // warp-local softmax stats over this warp's 8 distinct n
                float m = r;
                m = fmaxf(m, __shfl_xor_sync(0xFFFFFFFFu, m, 4));
                m = fmaxf(m, __shfl_xor_sync(0xFFFFFFFFu, m, 8));
                m = fmaxf(m, __shfl_xor_sync(0xFFFFFFFFu, m, 16));
                const float e = __expf(r - m);
                float S = e;
                S += __shfl_xor_sync(0xFFFFFFFFu, S, 4);
                S += __shfl_xor_sync(0xFFFFFFFFu, S, 8);
                S += __shfl_xor_sync(0xFFFFFFFFu, S, 16);
                if (l == 0) red[buf][w] = make_float2(m, S);
                __syncthreads();

                // block combine of 16 (m,S) pairs: lanes 0..15 hold one pair each
                const float2 rs = red[buf][l & 15];
                float mk = (l < 16) ? rs.x : -1e30f;
                float Sk = (l < 16) ? rs.y : 0.0f;
                float M = mk;
                M = fmaxf(M, __shfl_xor_sync(0xFFFFFFFFu, M, 1));
                M = fmaxf(M, __shfl_xor_sync(0xFFFFFFFFu, M, 2));
                M = fmaxf(M, __shfl_xor_sync(0xFFFFFFFFu, M, 4));
                M = fmaxf(M, __shfl_xor_sync(0xFFFFFFFFu, M, 8));
                M = fmaxf(M, __shfl_xor_sync(0xFFFFFFFFu, M, 16));
                float zk = Sk * __expf(mk - M);
                zk += __shfl_xor_sync(0xFFFFFFFFu, zk, 1);
                zk += __shfl_xor_sync(0xFFFFFFFFu, zk, 2);
                zk += __shfl_xor_sync(0xFFFFFFFFu, zk, 4);
                zk += __shfl_xor_sync(0xFFFFFFFFu, zk, 8);
                zk += __shfl_xor_sync(0xFFFFFFFFu, zk, 16);

                const float c = e * __expf(m - M) / zk;
#pragma unroll
                for (int j = 0; j < 4; ++j) sacc[bb][j] += c * pr[j];
                buf ^= 1;
            } else {
#pragma unroll
                for (int j = 0; j < 4; ++j) sacc[bb][j] += pr[j];
            }
        }
    }

    // write per-(iblock,b) partials; coalesced float4 per lane
#pragma unroll
    for (int bb = 0; bb < BG; ++bb) {
        float* gp = g_partial + ((size_t)blockIdx.x * BB + (b0 + bb)) * NDD + n * DD + dq;
        *(float4*)gp = make_float4(sacc[bb][0], sacc[bb][1], sacc[bb][2], sacc[bb][3]);
    }
}

// ---------------------------------------------------------------------------
// Reduce the NBI partials, scale, squash, write out. Thread per (b,n).
// ---------------------------------------------------------------------------
__global__ void reduce_squash_kernel(float* __restrict__ out, float scale)
{
    const int r = blockIdx.x * blockDim.x + threadIdx.x;   // r = b*128 + n
    if (r >= BB * N2) return;

    float s[16];
#pragma unroll
    for (int d = 0; d < 16; ++d) s[d] = 0.0f;

#pragma unroll 1
    for (int blk = 0; blk < NBI; ++blk) {
        const float4* pp = (const float4*)(g_partial + ((size_t)blk * BB * N2 + r) * DD);
#pragma unroll
        for (int q = 0; q < 4; ++q) {
            const float4 a = pp[q];
            s[4 * q + 0] += a.x; s[4 * q + 1] += a.y;
            s[4 * q + 2] += a.z; s[4 * q + 3] += a.w;
        }
    }
    float sq = 0.0f;
#pragma unroll
    for (int d = 0; d < 16; ++d) { s[d] *= scale; sq += s[d] * s[d]; }
    const float norm = sqrtf(sq + 1.1920929e-7f);
    const float f = sq / ((1.0f + sq) * norm);
#pragma unroll
    for (int d = 0; d < 16; ++d) out[(size_t)r * DD + d] = f * s[d];
}

// ---------------------------------------------------------------------------
extern "C" void kernel_launch(void* const* d_in, const int* in_sizes, int n_in,
                              void* d_out, int out_size)
{
    const float* x = (const float*)d_in[0];
    const float* W = (const float*)d_in[1];
    if (n_in >= 2 && in_sizes[0] > in_sizes[1]) {   // safety: x is the smaller tensor
        const float* t = x; x = W; W = t;
    }
    float* out = (float*)d_out;

    float* d_v0;
    cudaGetSymbolAddress((void**)&d_v0, g_v0);

    dim3 grid(NBI, NBB);

    // iteration 0: uniform coupling -> s0 = (1/128) * sum_i pred
    caps_pass<false><<<grid, NT>>>(x, W, nullptr);
    reduce_squash_kernel<<<32, 256>>>(d_v0, 1.0f / 128.0f);

    // iteration 1: softmax(agreement) routing, final squash -> output
    caps_pass<true><<<grid, NT>>>(x, W, d_v0);
    reduce_squash_kernel<<<32, 256>>>(out, 1.0f);
}

// round 4
// speedup vs baseline: 1.5877x; 1.5877x over previous
#include <cuda_runtime.h>
#include <cuda_bf16.h>
#include <math.h>

// Problem dims
#define BB   64
#define N1   1152
#define PP   8
#define N2   128
#define DD   16
#define NDD  (N2 * DD)          // 2048
#define WI4  4096               // float4s per i in W (16384 floats)

#define I_B  64                 // i's per block
#define BG   8                  // b's per block
#define NBI  (N1 / I_B)         // 18
#define NBB  (BB / BG)          // 8
#define NT   512                // 16 warps

// Scratch (no allocations allowed -> device globals)
__device__ float  g_partial[NBI * BB * NDD];     // 9.44 MB per-(iblock,b) partials
__device__ float  g_v0[BB * NDD];                // squashed v after iteration 0
__device__ float4 g_W2[(size_t)N1 * WI4];        // 75.5 MB repacked W

// ---------------------------------------------------------------------------
// Repack W so that main-pass warp loads are fully coalesced.
// Warp block (i, w) covers original float4s [i*4096 + w*256 + f), f = lane*8+q.
// New layout: dst[i*4096 + w*256 + q*32 + lane] = src[i*4096 + w*256 + lane*8 + q]
// Main pass then does wv[q] = W2p[q*32 + l]  (contiguous across lanes, nL=4).
// ---------------------------------------------------------------------------
__global__ __launch_bounds__(256) void repack_W(const float4* __restrict__ W)
{
    const int t = blockIdx.x * 256 + threadIdx.x;       // over N1*4096
    const int l = t & 31;
    const int q = (t >> 5) & 7;
    const int base = t & ~255;                          // i*4096 + w*256
    g_W2[t] = W[base + l * 8 + q];
}

// ---------------------------------------------------------------------------
// One kernel, two modes.
//   ROUTE=false: sacc += pred                      (iteration 0, c uniform)
//   ROUTE=true : raw=<pred,v0>, softmax_n (no max-sub), sacc += c*pred
// Mapping: warp w owns n in [8w,8w+8); lane l: n = 8w + (l>>2), d-quad (l&3)*4.
// Routing softmax: quad shfl (16 d) -> warp shfl (8 n) -> ONE barrier per ii
// combining 16 warps x 8 b via padded smem + shfl.
// ---------------------------------------------------------------------------
template<bool ROUTE>
__global__ __launch_bounds__(NT) void caps_pass(
    const float* __restrict__ x, const float* __restrict__ v0in)
{
    extern __shared__ float sm[];
    float* x_sh = sm;                                   // BG*I_B*PP = 4096 floats
    float* v0s  = sm + 4096;                            // ROUTE: BG*NDD = 16384 floats
    float* red  = sm + 4096 + (ROUTE ? 16384 : 0);      // ROUTE: 2*16*9 = 288 floats

    const int tid = threadIdx.x;
    const int w   = tid >> 5;
    const int l   = tid & 31;
    const int n   = w * 8 + (l >> 2);
    const int dq  = (l & 3) * 4;
    const int ib0 = blockIdx.x * I_B;
    const int b0  = blockIdx.y * BG;

    // stage x tile: x[b0+bb][ib0..ib0+64)[8]
    for (int t = tid; t < BG * I_B * PP; t += NT) {
        const int bb  = t >> 9;                         // I_B*PP = 512
        const int rem = t & 511;
        x_sh[t] = x[(size_t)(b0 + bb) * (N1 * PP) + (size_t)ib0 * PP + rem];
    }
    if (ROUTE) {
        for (int t = tid; t < BG * NDD; t += NT) {
            const int bb  = t >> 11;
            const int rem = t & 2047;
            v0s[t] = v0in[(size_t)(b0 + bb) * NDD + rem];
        }
    }
    __syncthreads();

    float sacc[BG][4];
#pragma unroll
    for (int bb = 0; bb < BG; ++bb)
#pragma unroll
        for (int j = 0; j < 4; ++j) sacc[bb][j] = 0.0f;

    int buf = 0;
#pragma unroll 1
    for (int ii = 0; ii < I_B; ++ii) {
        const float4* Wp = g_W2 + (((size_t)(ib0 + ii)) << 12) + (w << 8);

        if (!ROUTE) {
#pragma unroll
            for (int j = 0; j < 4; ++j) {
                const float4 w0 = Wp[(2 * j) * 32 + l];         // coalesced
                const float4 w1 = Wp[(2 * j + 1) * 32 + l];
#pragma unroll
                for (int bb = 0; bb < BG; ++bb) {
                    const float4 xa = *(const float4*)&x_sh[bb * 512 + ii * PP];
                    const float4 xb = *(const float4*)&x_sh[bb * 512 + ii * PP + 4];
                    sacc[bb][j] += w0.x * xa.x + w0.y * xa.y + w0.z * xa.z + w0.w * xa.w
                                 + w1.x * xb.x + w1.y * xb.y + w1.z * xb.z + w1.w * xb.w;
                }
            }
        } else {
            float pr[BG][4];
#pragma unroll
            for (int j = 0; j < 4; ++j) {
                const float4 w0 = Wp[(2 * j) * 32 + l];
                const float4 w1 = Wp[(2 * j + 1) * 32 + l];
#pragma unroll
                for (int bb = 0; bb < BG; ++bb) {
                    const float4 xa = *(const float4*)&x_sh[bb * 512 + ii * PP];
                    const float4 xb = *(const float4*)&x_sh[bb * 512 + ii * PP + 4];
                    pr[bb][j] = w0.x * xa.x + w0.y * xa.y + w0.z * xa.z + w0.w * xa.w
                              + w1.x * xb.x + w1.y * xb.y + w1.z * xb.z + w1.w * xb.w;
                }
            }

            // per-b agreement + exp + warp partial sum; fold e into pred
#pragma unroll
            for (int bb = 0; bb < BG; ++bb) {
                const float4 vv = *(const float4*)&v0s[bb * NDD + n * DD + dq];
                float r = pr[bb][0] * vv.x + pr[bb][1] * vv.y
                        + pr[bb][2] * vv.z + pr[bb][3] * vv.w;
                r += __shfl_xor_sync(0xFFFFFFFFu, r, 1);
                r += __shfl_xor_sync(0xFFFFFFFFu, r, 2);      // quad: full 16-d dot
                const float e = __expf(r);                    // no max-sub (|r| < ~50)
                float S = e;
                S += __shfl_xor_sync(0xFFFFFFFFu, S, 4);
                S += __shfl_xor_sync(0xFFFFFFFFu, S, 8);
                S += __shfl_xor_sync(0xFFFFFFFFu, S, 16);     // 4 * sum over warp's 8 n
                if (l == 0) red[(buf * 16 + w) * 9 + bb] = S;
                pr[bb][0] *= e; pr[bb][1] *= e; pr[bb][2] *= e; pr[bb][3] *= e;
            }
            __syncthreads();                                  // ONE barrier per ii

            // block combine: 16 warp sums per b (stride-9 pad -> conflict-free)
#pragma unroll
            for (int bb = 0; bb < BG; ++bb) {
                float sv = red[(buf * 16 + (l & 15)) * 9 + bb];
                sv += __shfl_xor_sync(0xFFFFFFFFu, sv, 1);
                sv += __shfl_xor_sync(0xFFFFFFFFu, sv, 2);
                sv += __shfl_xor_sync(0xFFFFFFFFu, sv, 4);
                sv += __shfl_xor_sync(0xFFFFFFFFu, sv, 8);    // = 4 * sum_{128 n} e
                const float c4 = 4.0f / sv;                   // c = e * 4/sv
                sacc[bb][0] += c4 * pr[bb][0];
                sacc[bb][1] += c4 * pr[bb][1];
                sacc[bb][2] += c4 * pr[bb][2];
                sacc[bb][3] += c4 * pr[bb][3];
            }
            buf ^= 1;                                         // WAR-safe double buffer
        }
    }

    // write per-(iblock,b) partials
#pragma unroll
    for (int bb = 0; bb < BG; ++bb) {
        float* gp = g_partial + ((size_t)blockIdx.x * BB + (b0 + bb)) * NDD + n * DD + dq;
        *(float4*)gp = make_float4(sacc[bb][0], sacc[bb][1], sacc[bb][2], sacc[bb][3]);
    }
}

// ---------------------------------------------------------------------------
// Reduce the NBI partials, scale, squash, write out.
// 4 lanes per (b,n) row (one d-quad each); quad shuffles for the norm.
// ---------------------------------------------------------------------------
__global__ __launch_bounds__(256) void reduce_squash_kernel(float* __restrict__ out, float scale)
{
    const int t = blockIdx.x * 256 + threadIdx.x;   // 32768 threads
    const int r = t >> 2;                           // row = b*128 + n
    const int quad = t & 3;

    float4 s = make_float4(0.f, 0.f, 0.f, 0.f);
#pragma unroll 1
    for (int blk = 0; blk < NBI; ++blk) {
        const float4 a = *(const float4*)(g_partial
            + ((size_t)blk * (BB * N2) + r) * DD + quad * 4);
        s.x += a.x; s.y += a.y; s.z += a.z; s.w += a.w;
    }
    s.x *= scale; s.y *= scale; s.z *= scale; s.w *= scale;

    float sq = s.x * s.x + s.y * s.y + s.z * s.z + s.w * s.w;
    sq += __shfl_xor_sync(0xFFFFFFFFu, sq, 1);
    sq += __shfl_xor_sync(0xFFFFFFFFu, sq, 2);      // full 16-d squared norm

    const float norm = sqrtf(sq + 1.1920929e-7f);
    const float f = sq / ((1.0f + sq) * norm);
    *(float4*)(out + (size_t)r * DD + quad * 4) =
        make_float4(f * s.x, f * s.y, f * s.z, f * s.w);
}

// ---------------------------------------------------------------------------
extern "C" void kernel_launch(void* const* d_in, const int* in_sizes, int n_in,
                              void* d_out, int out_size)
{
    const float* x = (const float*)d_in[0];
    const float* W = (const float*)d_in[1];
    if (n_in >= 2 && in_sizes[0] > in_sizes[1]) {   // safety: x is the smaller tensor
        const float* t = x; x = W; W = t;
    }
    float* out = (float*)d_out;

    float* d_v0;
    cudaGetSymbolAddress((void**)&d_v0, g_v0);

    const int smem0 = 4096 * 4;                      // pass 0: x tile only
    const int smem1 = (4096 + 16384 + 288) * 4;      // routing: + v0 + red = 82.9 KB
    cudaFuncSetAttribute(caps_pass<true>,
                         cudaFuncAttributeMaxDynamicSharedMemorySize, smem1);

    // repack W into warp-coalesced layout (per-launch, ~20us)
    repack_W<<<(N1 * WI4) / 256, 256>>>((const float4*)W);

    dim3 grid(NBI, NBB);

    // iteration 0: uniform coupling -> s0 = (1/128) * sum_i pred
    caps_pass<false><<<grid, NT, smem0>>>(x, nullptr);
    reduce_squash_kernel<<<128, 256>>>(d_v0, 1.0f / 128.0f);

    // iteration 1: softmax(agreement) routing, final squash -> output
    caps_pass<true><<<grid, NT, smem1>>>(x, d_v0);
    reduce_squash_kernel<<<128, 256>>>(out, 1.0f);
}